// round 7
// baseline (speedup 1.0000x reference)
#include <cuda_runtime.h>
#include <cuda_bf16.h>
#include <cstdint>

#define MAX_N 100000

// Device scratch (no cudaMalloc allowed).
__device__ float g_diag[MAX_N];
__device__ float g_deg[MAX_N];   // degree, then overwritten with 1/degree

// ---------------------------------------------------------------------------
// K0: zero the degree accumulator
// ---------------------------------------------------------------------------
__global__ void zero_deg_kernel(int n) {
    int i = blockIdx.x * blockDim.x + threadIdx.x;
    if (i < n) g_deg[i] = 0.0f;
}

// ---------------------------------------------------------------------------
// K1 (fused): blocks [0, diag_blocks) compute diag = sigmoid(x@w+b)
//             blocks [diag_blocks, ...) compute degree histogram
// diag: warp handles 4 consecutive rows -> 8 float4 loads in flight/lane,
// 32 rows per 256-thread block.
// ---------------------------------------------------------------------------
__global__ void diag_deg_kernel(const float* __restrict__ x,
                                const float* __restrict__ w,
                                const float* __restrict__ b,
                                int n, int diag_blocks,
                                const int* __restrict__ col, int E) {
    if ((int)blockIdx.x < diag_blocks) {
        // ---- diag: 4 rows per warp, D=256 fixed ----
        __shared__ float sw[256];
        if (threadIdx.x < 256) sw[threadIdx.x] = w[threadIdx.x];
        __syncthreads();

        int warp = threadIdx.x >> 5;
        int lane = threadIdx.x & 31;
        int r0   = (blockIdx.x * 8 + warp) * 4;   // first of 4 rows
        if (r0 >= n) return;

        const float4* wf = reinterpret_cast<const float4*>(sw);
        const float4* x0 = reinterpret_cast<const float4*>(x + (size_t)r0 * 256);

        float acc0 = 0.f, acc1 = 0.f, acc2 = 0.f, acc3 = 0.f;
        bool ok1 = (r0 + 1) < n, ok2 = (r0 + 2) < n, ok3 = (r0 + 3) < n;

        #pragma unroll
        for (int it = 0; it < 2; ++it) {
            int o = lane + it * 32;              // float4 offset within a row
            float4 wv = wf[o];
            float4 a  = x0[o];                   // row r0
            float4 bv = ok1 ? x0[64 + o]  : make_float4(0,0,0,0);
            float4 c  = ok2 ? x0[128 + o] : make_float4(0,0,0,0);
            float4 dv = ok3 ? x0[192 + o] : make_float4(0,0,0,0);
            acc0 += a.x * wv.x + a.y * wv.y + a.z * wv.z + a.w * wv.w;
            acc1 += bv.x * wv.x + bv.y * wv.y + bv.z * wv.z + bv.w * wv.w;
            acc2 += c.x * wv.x + c.y * wv.y + c.z * wv.z + c.w * wv.w;
            acc3 += dv.x * wv.x + dv.y * wv.y + dv.z * wv.z + dv.w * wv.w;
        }

        #pragma unroll
        for (int off = 16; off > 0; off >>= 1) {
            acc0 += __shfl_xor_sync(0xFFFFFFFFu, acc0, off);
            acc1 += __shfl_xor_sync(0xFFFFFFFFu, acc1, off);
            acc2 += __shfl_xor_sync(0xFFFFFFFFu, acc2, off);
            acc3 += __shfl_xor_sync(0xFFFFFFFFu, acc3, off);
        }

        if (lane < 4) {
            float acc = (lane == 0) ? acc0 : (lane == 1) ? acc1
                       : (lane == 2) ? acc2 : acc3;
            int r = r0 + lane;
            if (r < n) {
                float z = acc + __ldg(b);
                g_diag[r] = 1.0f / (1.0f + __expf(-z));
            }
        }
    } else {
        // ---- degree histogram: 4 edges per thread, int4 loads ----
        int tb   = blockIdx.x - diag_blocks;
        int i    = tb * blockDim.x + threadIdx.x;
        int base = i * 4;
        if (base + 3 < E) {
            int4 c = *reinterpret_cast<const int4*>(col + base);
            atomicAdd(&g_deg[c.x], 1.0f);
            atomicAdd(&g_deg[c.y], 1.0f);
            atomicAdd(&g_deg[c.z], 1.0f);
            atomicAdd(&g_deg[c.w], 1.0f);
        } else {
            for (int k = base; k < E; ++k)
                atomicAdd(&g_deg[col[k]], 1.0f);
        }
    }
}

// ---------------------------------------------------------------------------
// K2: g_deg <- 1/g_deg (in place)
// ---------------------------------------------------------------------------
__global__ void recip_deg_kernel(int n) {
    int i = blockIdx.x * blockDim.x + threadIdx.x;
    if (i < n) g_deg[i] = 1.0f / g_deg[i];
}

// ---------------------------------------------------------------------------
// K3: adj_val[e] = deginv[row] * edge_attr[e] * diag[col]
// 8 edges per thread: 16 independent gathers in flight.
// ---------------------------------------------------------------------------
__global__ void final_kernel(const int* __restrict__ row_idx,
                             const int* __restrict__ col_idx,
                             const float* __restrict__ edge_attr,
                             float* __restrict__ out,
                             int E, int write_index) {
    int i    = blockIdx.x * blockDim.x + threadIdx.x;
    int base = i * 8;

    if (base + 7 < E) {
        int4   ra = *reinterpret_cast<const int4*>(row_idx + base);
        int4   rb = *reinterpret_cast<const int4*>(row_idx + base + 4);
        int4   ca = *reinterpret_cast<const int4*>(col_idx + base);
        int4   cb = *reinterpret_cast<const int4*>(col_idx + base + 4);
        float4 aa = *reinterpret_cast<const float4*>(edge_attr + base);
        float4 ab = *reinterpret_cast<const float4*>(edge_attr + base + 4);

        // 16 independent gathers (tables L2-resident)
        float di0 = __ldg(&g_deg[ra.x]),  di1 = __ldg(&g_deg[ra.y]);
        float di2 = __ldg(&g_deg[ra.z]),  di3 = __ldg(&g_deg[ra.w]);
        float di4 = __ldg(&g_deg[rb.x]),  di5 = __ldg(&g_deg[rb.y]);
        float di6 = __ldg(&g_deg[rb.z]),  di7 = __ldg(&g_deg[rb.w]);
        float dg0 = __ldg(&g_diag[ca.x]), dg1 = __ldg(&g_diag[ca.y]);
        float dg2 = __ldg(&g_diag[ca.z]), dg3 = __ldg(&g_diag[ca.w]);
        float dg4 = __ldg(&g_diag[cb.x]), dg5 = __ldg(&g_diag[cb.y]);
        float dg6 = __ldg(&g_diag[cb.z]), dg7 = __ldg(&g_diag[cb.w]);

        float4 va, vb;
        va.x = aa.x * dg0 * di0;  va.y = aa.y * dg1 * di1;
        va.z = aa.z * dg2 * di2;  va.w = aa.w * dg3 * di3;
        vb.x = ab.x * dg4 * di4;  vb.y = ab.y * dg5 * di5;
        vb.z = ab.z * dg6 * di6;  vb.w = ab.w * dg7 * di7;

        if (write_index) {
            *reinterpret_cast<float4*>(out + base) =
                make_float4((float)ra.x, (float)ra.y, (float)ra.z, (float)ra.w);
            *reinterpret_cast<float4*>(out + base + 4) =
                make_float4((float)rb.x, (float)rb.y, (float)rb.z, (float)rb.w);
            *reinterpret_cast<float4*>(out + E + base) =
                make_float4((float)ca.x, (float)ca.y, (float)ca.z, (float)ca.w);
            *reinterpret_cast<float4*>(out + E + base + 4) =
                make_float4((float)cb.x, (float)cb.y, (float)cb.z, (float)cb.w);
            *reinterpret_cast<float4*>(out + 2 * E + base)     = va;
            *reinterpret_cast<float4*>(out + 2 * E + base + 4) = vb;
        } else {
            *reinterpret_cast<float4*>(out + base)     = va;
            *reinterpret_cast<float4*>(out + base + 4) = vb;
        }
    } else {
        for (int k = base; k < E; ++k) {
            int r = row_idx[k];
            int c = col_idx[k];
            float v = edge_attr[k] * g_diag[c] * g_deg[r];
            if (write_index) {
                out[k]         = (float)r;
                out[E + k]     = (float)c;
                out[2 * E + k] = v;
            } else {
                out[k] = v;
            }
        }
    }
}

// ---------------------------------------------------------------------------
// launch
// ---------------------------------------------------------------------------
extern "C" void kernel_launch(void* const* d_in, const int* in_sizes, int n_in,
                              void* d_out, int out_size) {
    const float* x          = (const float*)d_in[0];
    const int*   edge_index = (const int*)d_in[1];
    const float* edge_attr  = (const float*)d_in[2];
    const float* w          = (const float*)d_in[3];
    const float* b          = (const float*)d_in[4];
    float*       out        = (float*)d_out;

    int D = in_sizes[3];
    int N = in_sizes[0] / D;
    int E = in_sizes[2];

    const int* row_idx = edge_index;
    const int* col_idx = edge_index + E;

    // K0: zero degrees
    zero_deg_kernel<<<(N + 255) / 256, 256>>>(N);

    // K1: fused diag (4 rows/warp -> 32 rows/block) + degree histogram
    int diag_blocks = (N + 31) / 32;
    int deg_threads = (E + 3) / 4;
    int deg_blocks  = (deg_threads + 255) / 256;
    diag_deg_kernel<<<diag_blocks + deg_blocks, 256>>>(
        x, w, b, N, diag_blocks, col_idx, E);

    // K2: reciprocal of degree
    recip_deg_kernel<<<(N + 255) / 256, 256>>>(N);

    // K3: final edge values, 8 edges/thread
    int write_index = (out_size >= 3 * E) ? 1 : 0;
    int fin_threads = (E + 7) / 8;
    final_kernel<<<(fin_threads + 255) / 256, 256>>>(
        row_idx, col_idx, edge_attr, out, E, write_index);
}

// round 9
// speedup vs baseline: 1.4596x; 1.4596x over previous
#include <cuda_runtime.h>
#include <cuda_bf16.h>
#include <cstdint>

#define MAX_N 100000

// Device scratch (no cudaMalloc allowed).
__device__ float g_diag[MAX_N];
__device__ float g_deg[MAX_N];   // degree, then overwritten with 1/degree

// ---------------------------------------------------------------------------
// K0: zero the degree accumulator
// ---------------------------------------------------------------------------
__global__ void zero_deg_kernel(int n) {
    int i = blockIdx.x * blockDim.x + threadIdx.x;
    if (i < n) g_deg[i] = 0.0f;
}

// ---------------------------------------------------------------------------
// K1 (fused): blocks [0, diag_blocks) compute diag = sigmoid(x@w+b)
//             blocks [diag_blocks, ...) compute degree histogram
// diag: warp handles 4 consecutive rows -> 8 float4 loads in flight/lane.
// ---------------------------------------------------------------------------
__global__ void diag_deg_kernel(const float* __restrict__ x,
                                const float* __restrict__ w,
                                const float* __restrict__ b,
                                int n, int diag_blocks,
                                const int* __restrict__ col, int E) {
    if ((int)blockIdx.x < diag_blocks) {
        // ---- diag: 4 rows per warp, D=256 fixed ----
        __shared__ float sw[256];
        if (threadIdx.x < 256) sw[threadIdx.x] = w[threadIdx.x];
        __syncthreads();

        int warp = threadIdx.x >> 5;
        int lane = threadIdx.x & 31;
        int r0   = (blockIdx.x * 8 + warp) * 4;   // first of 4 rows
        if (r0 >= n) return;

        const float4* wf = reinterpret_cast<const float4*>(sw);
        const float4* x0 = reinterpret_cast<const float4*>(x + (size_t)r0 * 256);

        float acc0 = 0.f, acc1 = 0.f, acc2 = 0.f, acc3 = 0.f;
        bool ok1 = (r0 + 1) < n, ok2 = (r0 + 2) < n, ok3 = (r0 + 3) < n;

        #pragma unroll
        for (int it = 0; it < 2; ++it) {
            int o = lane + it * 32;              // float4 offset within a row
            float4 wv = wf[o];
            float4 a  = x0[o];                   // row r0
            float4 bv = ok1 ? x0[64 + o]  : make_float4(0,0,0,0);
            float4 c  = ok2 ? x0[128 + o] : make_float4(0,0,0,0);
            float4 dv = ok3 ? x0[192 + o] : make_float4(0,0,0,0);
            acc0 += a.x * wv.x + a.y * wv.y + a.z * wv.z + a.w * wv.w;
            acc1 += bv.x * wv.x + bv.y * wv.y + bv.z * wv.z + bv.w * wv.w;
            acc2 += c.x * wv.x + c.y * wv.y + c.z * wv.z + c.w * wv.w;
            acc3 += dv.x * wv.x + dv.y * wv.y + dv.z * wv.z + dv.w * wv.w;
        }

        #pragma unroll
        for (int off = 16; off > 0; off >>= 1) {
            acc0 += __shfl_xor_sync(0xFFFFFFFFu, acc0, off);
            acc1 += __shfl_xor_sync(0xFFFFFFFFu, acc1, off);
            acc2 += __shfl_xor_sync(0xFFFFFFFFu, acc2, off);
            acc3 += __shfl_xor_sync(0xFFFFFFFFu, acc3, off);
        }

        if (lane < 4) {
            float acc = (lane == 0) ? acc0 : (lane == 1) ? acc1
                       : (lane == 2) ? acc2 : acc3;
            int r = r0 + lane;
            if (r < n) {
                float z = acc + __ldg(b);
                g_diag[r] = 1.0f / (1.0f + __expf(-z));
            }
        }
    } else {
        // ---- degree histogram: 4 edges per thread, int4 loads ----
        int tb   = blockIdx.x - diag_blocks;
        int i    = tb * blockDim.x + threadIdx.x;
        int base = i * 4;
        if (base + 3 < E) {
            int4 c = *reinterpret_cast<const int4*>(col + base);
            atomicAdd(&g_deg[c.x], 1.0f);
            atomicAdd(&g_deg[c.y], 1.0f);
            atomicAdd(&g_deg[c.z], 1.0f);
            atomicAdd(&g_deg[c.w], 1.0f);
        } else {
            for (int k = base; k < E; ++k)
                atomicAdd(&g_deg[col[k]], 1.0f);
        }
    }
}

// ---------------------------------------------------------------------------
// K2: g_deg <- 1/g_deg (in place)
// ---------------------------------------------------------------------------
__global__ void recip_deg_kernel(int n) {
    int i = blockIdx.x * blockDim.x + threadIdx.x;
    if (i < n) g_deg[i] = 1.0f / g_deg[i];
}

// ---------------------------------------------------------------------------
// K3: adj_val[e] = deginv[row] * edge_attr[e] * diag[col]
// 4 edges per thread: 8 independent gathers, max warps in flight (TLP is
// what hides gather latency here, not per-thread ILP).
// ---------------------------------------------------------------------------
__global__ void final_kernel(const int* __restrict__ row_idx,
                             const int* __restrict__ col_idx,
                             const float* __restrict__ edge_attr,
                             float* __restrict__ out,
                             int E, int write_index) {
    int i    = blockIdx.x * blockDim.x + threadIdx.x;
    int base = i * 4;

    if (base + 3 < E) {
        int4   r4 = *reinterpret_cast<const int4*>(row_idx + base);
        int4   c4 = *reinterpret_cast<const int4*>(col_idx + base);
        float4 a4 = *reinterpret_cast<const float4*>(edge_attr + base);

        float di0 = __ldg(&g_deg[r4.x]),  di1 = __ldg(&g_deg[r4.y]);
        float di2 = __ldg(&g_deg[r4.z]),  di3 = __ldg(&g_deg[r4.w]);
        float dg0 = __ldg(&g_diag[c4.x]), dg1 = __ldg(&g_diag[c4.y]);
        float dg2 = __ldg(&g_diag[c4.z]), dg3 = __ldg(&g_diag[c4.w]);

        float4 v;
        v.x = a4.x * dg0 * di0;
        v.y = a4.y * dg1 * di1;
        v.z = a4.z * dg2 * di2;
        v.w = a4.w * dg3 * di3;

        if (write_index) {
            *reinterpret_cast<float4*>(out + base) =
                make_float4((float)r4.x, (float)r4.y, (float)r4.z, (float)r4.w);
            *reinterpret_cast<float4*>(out + E + base) =
                make_float4((float)c4.x, (float)c4.y, (float)c4.z, (float)c4.w);
            *reinterpret_cast<float4*>(out + 2 * E + base) = v;
        } else {
            *reinterpret_cast<float4*>(out + base) = v;
        }
    } else {
        for (int k = base; k < E; ++k) {
            int r = row_idx[k];
            int c = col_idx[k];
            float v = edge_attr[k] * g_diag[c] * g_deg[r];
            if (write_index) {
                out[k]         = (float)r;
                out[E + k]     = (float)c;
                out[2 * E + k] = v;
            } else {
                out[k] = v;
            }
        }
    }
}

// ---------------------------------------------------------------------------
// launch
// ---------------------------------------------------------------------------
extern "C" void kernel_launch(void* const* d_in, const int* in_sizes, int n_in,
                              void* d_out, int out_size) {
    const float* x          = (const float*)d_in[0];
    const int*   edge_index = (const int*)d_in[1];
    const float* edge_attr  = (const float*)d_in[2];
    const float* w          = (const float*)d_in[3];
    const float* b          = (const float*)d_in[4];
    float*       out        = (float*)d_out;

    int D = in_sizes[3];
    int N = in_sizes[0] / D;
    int E = in_sizes[2];

    const int* row_idx = edge_index;
    const int* col_idx = edge_index + E;

    // K0: zero degrees
    zero_deg_kernel<<<(N + 255) / 256, 256>>>(N);

    // K1: fused diag (4 rows/warp -> 32 rows/block) + degree histogram
    int diag_blocks = (N + 31) / 32;
    int deg_threads = (E + 3) / 4;
    int deg_blocks  = (deg_threads + 255) / 256;
    diag_deg_kernel<<<diag_blocks + deg_blocks, 256>>>(
        x, w, b, N, diag_blocks, col_idx, E);

    // K2: reciprocal of degree
    recip_deg_kernel<<<(N + 255) / 256, 256>>>(N);

    // K3: final edge values, 4 edges/thread
    int write_index = (out_size >= 3 * E) ? 1 : 0;
    int fin_threads = (E + 3) / 4;
    final_kernel<<<(fin_threads + 255) / 256, 256>>>(
        row_idx, col_idx, edge_attr, out, E, write_index);
}